// round 1
// baseline (speedup 1.0000x reference)
#include <cuda_runtime.h>
#include <cuda_bf16.h>

#define HW   240
#define PSZ  20
#define GSZ  12
#define NPATCH (GSZ * GSZ)          // 144
#define SEGS_PER_IMG (HW * GSZ)     // 240 rows * 12 segs = 2880

// Global scratch: [0..143] = per-patch sum, [144..287] = per-patch sumsq (doubles)
__device__ double g_acc[2 * NPATCH];

__global__ void zero_acc_kernel() {
    int t = blockIdx.x * blockDim.x + threadIdx.x;
    if (t < 2 * NPATCH) g_acc[t] = 0.0;
}

// One thread = one 20-float patch-row segment (5x float4, contiguous).
// Segments tile pred linearly: float offset = seg * 20.
__global__ void patch_sums_kernel(const float* __restrict__ pred, int nseg) {
    __shared__ float s_s[NPATCH];
    __shared__ float s_ss[NPATCH];
    for (int i = threadIdx.x; i < NPATCH; i += blockDim.x) {
        s_s[i] = 0.0f;
        s_ss[i] = 0.0f;
    }
    __syncthreads();

    for (int seg = blockIdx.x * blockDim.x + threadIdx.x; seg < nseg;
         seg += gridDim.x * blockDim.x) {
        const float4* p4 = reinterpret_cast<const float4*>(pred + (size_t)seg * PSZ);
        float s = 0.0f, ss = 0.0f;
#pragma unroll
        for (int k = 0; k < 5; k++) {
            float4 v = __ldcs(&p4[k]);
            s  += (v.x + v.y) + (v.z + v.w);
            ss += (v.x * v.x + v.y * v.y) + (v.z * v.z + v.w * v.w);
        }
        // seg = b*2880 + y*12 + g2 ; g1 = y/20 -> patch = (t/240)*12 + t%12
        int t  = seg % SEGS_PER_IMG;
        int pi = (t / (PSZ * GSZ)) * GSZ + (t % GSZ);
        atomicAdd(&s_s[pi],  s);
        atomicAdd(&s_ss[pi], ss);
    }
    __syncthreads();

    for (int i = threadIdx.x; i < NPATCH; i += blockDim.x) {
        float s = s_s[i], ss = s_ss[i];
        if (s != 0.0f || ss != 0.0f) {
            atomicAdd(&g_acc[i],          (double)s);
            atomicAdd(&g_acc[NPATCH + i], (double)ss);
        }
    }
}

// Single block: gt patch sums (cooperative), global mean, loss.
__global__ void finalize_kernel(const float* __restrict__ gt, float* __restrict__ out,
                                int B) {
    __shared__ float  gt_s[NPATCH];
    __shared__ float  gt_ss[NPATCH];
    __shared__ double red[256];
    __shared__ double sh_m;

    int t = threadIdx.x;
    for (int i = t; i < NPATCH; i += blockDim.x) {
        gt_s[i] = 0.0f;
        gt_ss[i] = 0.0f;
    }
    __syncthreads();

    // gt has SEGS_PER_IMG (2880) segments of 20 contiguous floats
    for (int seg = t; seg < SEGS_PER_IMG; seg += blockDim.x) {
        const float4* p4 = reinterpret_cast<const float4*>(gt + (size_t)seg * PSZ);
        float s = 0.0f, ss = 0.0f;
#pragma unroll
        for (int k = 0; k < 5; k++) {
            float4 v = p4[k];
            s  += (v.x + v.y) + (v.z + v.w);
            ss += (v.x * v.x + v.y * v.y) + (v.z * v.z + v.w * v.w);
        }
        int pi = (seg / (PSZ * GSZ)) * GSZ + (seg % GSZ);
        atomicAdd(&gt_s[pi],  s);
        atomicAdd(&gt_ss[pi], ss);
    }
    __syncthreads();

    // total pred sum -> global mean m
    red[t] = (t < NPATCH) ? g_acc[t] : 0.0;
    __syncthreads();
    for (int off = 128; off > 0; off >>= 1) {
        if (t < off) red[t] += red[t + off];
        __syncthreads();
    }
    if (t == 0) {
        double ntot = (double)B * HW * HW;
        sh_m = red[0] / ntot;
    }
    __syncthreads();
    double m = sh_m;

    double contrib = 0.0;
    if (t < NPATCH) {
        double n_pred = (double)B * PSZ * PSZ;
        double ps = g_acc[t];
        double pss = g_acc[NPATCH + t];
        double pv = pss / n_pred - 2.0 * m * (ps / n_pred) + m * m;

        double n_gt = (double)(PSZ * PSZ);
        double gs = (double)gt_s[t];
        double gss = (double)gt_ss[t];
        double gv = gss / n_gt - 2.0 * m * (gs / n_gt) + m * m;

        double d = pv - gv;
        contrib = d * d;
    }
    __syncthreads();
    red[t] = contrib;
    __syncthreads();
    for (int off = 128; off > 0; off >>= 1) {
        if (t < off) red[t] += red[t + off];
        __syncthreads();
    }
    if (t == 0) {
        out[0] = (float)(red[0] * 0.5 / 12.0);
    }
}

extern "C" void kernel_launch(void* const* d_in, const int* in_sizes, int n_in,
                              void* d_out, int out_size) {
    const float* pred = (const float*)d_in[0];
    const float* gt   = (const float*)d_in[1];
    float* out        = (float*)d_out;

    int B = in_sizes[0] / (HW * HW);
    int nseg = B * SEGS_PER_IMG;

    zero_acc_kernel<<<1, 2 * NPATCH>>>();

    int threads = 256;
    int blocks = 2960;                       // ~20 blocks/SM-wave worth of work
    int max_blocks = (nseg + threads - 1) / threads;
    if (blocks > max_blocks) blocks = max_blocks;
    patch_sums_kernel<<<blocks, threads>>>(pred, nseg);

    finalize_kernel<<<1, 256>>>(gt, out, B);
}

// round 2
// speedup vs baseline: 1.2246x; 1.2246x over previous
#include <cuda_runtime.h>
#include <cuda_bf16.h>

#define HW   240
#define PSZ  20
#define GSZ  12
#define NPATCH (GSZ * GSZ)            // 144
#define STRIPS_PER_IMG 720            // 12 bands * 60 strips (4 cols each)
#define IMG_ELEMS (HW * HW)           // 57600

// [0..143] pred sum, [144..287] pred sumsq, [288..431] gt sum, [432..575] gt sumsq
// Zero at module load; finalize_kernel re-zeros after use -> graph-replay safe.
__device__ double g_acc[4 * NPATCH];

// One thread = one 4-col x 20-row strip of a patch (20 float4 loads, stride 240 floats).
// Consecutive threads -> consecutive float4s per row-step: fully coalesced 512B requests.
__global__ void patch_sums_kernel(const float* __restrict__ pred,
                                  const float* __restrict__ gt,
                                  int pred_blocks, int nstrips_pred) {
    __shared__ float s_s[NPATCH];
    __shared__ float s_ss[NPATCH];
    for (int i = threadIdx.x; i < NPATCH; i += blockDim.x) {
        s_s[i] = 0.0f;
        s_ss[i] = 0.0f;
    }
    __syncthreads();

    const float* src;
    int accOff, id, nmax;
    if (blockIdx.x < pred_blocks) {
        src = pred; accOff = 0;
        id = blockIdx.x * blockDim.x + threadIdx.x;
        nmax = nstrips_pred;
    } else {
        src = gt; accOff = 2 * NPATCH;
        id = (blockIdx.x - pred_blocks) * blockDim.x + threadIdx.x;
        nmax = STRIPS_PER_IMG;
    }

    if (id < nmax) {
        int img  = id / STRIPS_PER_IMG;
        int rem  = id % STRIPS_PER_IMG;
        int band = rem / 60;            // patch row g1
        int s    = rem % 60;            // float4 column index
        int patch = band * GSZ + s / 5; // g1*12 + g2

        const float4* p4 = reinterpret_cast<const float4*>(
            src + (size_t)img * IMG_ELEMS + (size_t)band * (PSZ * HW) + (size_t)s * 4);

        float s0 = 0.f, s1 = 0.f, q0 = 0.f, q1 = 0.f;
#pragma unroll
        for (int r = 0; r < PSZ; r += 2) {
            float4 a = __ldcs(&p4[(size_t)r * 60]);
            float4 b = __ldcs(&p4[(size_t)(r + 1) * 60]);
            s0 += (a.x + a.y) + (a.z + a.w);
            q0 += (a.x * a.x + a.y * a.y) + (a.z * a.z + a.w * a.w);
            s1 += (b.x + b.y) + (b.z + b.w);
            q1 += (b.x * b.x + b.y * b.y) + (b.z * b.z + b.w * b.w);
        }
        atomicAdd(&s_s[patch],  s0 + s1);
        atomicAdd(&s_ss[patch], q0 + q1);
    }
    __syncthreads();

    for (int i = threadIdx.x; i < NPATCH; i += blockDim.x) {
        float a = s_s[i], b = s_ss[i];
        if (a != 0.0f || b != 0.0f) {
            atomicAdd(&g_acc[accOff + i],          (double)a);
            atomicAdd(&g_acc[accOff + NPATCH + i], (double)b);
        }
    }
}

// Single block: combine accumulators, compute loss, re-zero scratch.
__global__ void finalize_kernel(float* __restrict__ out, int B) {
    __shared__ double red[256];
    __shared__ double sh_m;
    int t = threadIdx.x;

    // total pred sum -> global mean m
    red[t] = (t < NPATCH) ? g_acc[t] : 0.0;
    __syncthreads();
    for (int off = 128; off > 0; off >>= 1) {
        if (t < off) red[t] += red[t + off];
        __syncthreads();
    }
    if (t == 0) sh_m = red[0] / ((double)B * IMG_ELEMS);
    __syncthreads();
    double m = sh_m;

    double contrib = 0.0;
    if (t < NPATCH) {
        double n_pred = (double)B * PSZ * PSZ;
        double pv = g_acc[NPATCH + t] / n_pred
                  - 2.0 * m * (g_acc[t] / n_pred) + m * m;
        double n_gt = (double)(PSZ * PSZ);
        double gv = g_acc[3 * NPATCH + t] / n_gt
                  - 2.0 * m * (g_acc[2 * NPATCH + t] / n_gt) + m * m;
        double d = pv - gv;
        contrib = d * d;
    }
    __syncthreads();
    red[t] = contrib;
    __syncthreads();
    for (int off = 128; off > 0; off >>= 1) {
        if (t < off) red[t] += red[t + off];
        __syncthreads();
    }
    if (t == 0) out[0] = (float)(red[0] * 0.5 / 12.0);

    // re-zero scratch for the next graph replay
    __syncthreads();
    for (int i = t; i < 4 * NPATCH; i += blockDim.x) g_acc[i] = 0.0;
}

extern "C" void kernel_launch(void* const* d_in, const int* in_sizes, int n_in,
                              void* d_out, int out_size) {
    const float* pred = (const float*)d_in[0];
    const float* gt   = (const float*)d_in[1];
    float* out        = (float*)d_out;

    int B = in_sizes[0] / IMG_ELEMS;
    int nstrips_pred = B * STRIPS_PER_IMG;           // 368640 for B=512

    int threads = 256;
    int pred_blocks = (nstrips_pred + threads - 1) / threads;   // 1440
    int gt_blocks   = (STRIPS_PER_IMG + threads - 1) / threads; // 3

    patch_sums_kernel<<<pred_blocks + gt_blocks, threads>>>(pred, gt, pred_blocks,
                                                            nstrips_pred);
    finalize_kernel<<<1, 256>>>(out, B);
}

// round 3
// speedup vs baseline: 1.2901x; 1.0534x over previous
#include <cuda_runtime.h>
#include <cuda_bf16.h>

#define HW   240
#define PSZ  20
#define GSZ  12
#define NPATCH (GSZ * GSZ)            // 144
#define STRIPS_PER_IMG 720            // 12 bands * 60 float4-strips
#define IMG_ELEMS (HW * HW)           // 57600

// [0..143] pred sum, [144..287] pred sumsq, [288..431] gt sum, [432..575] gt sumsq
// Zero at module load; last block re-zeros after use -> graph-replay safe.
__device__ double g_acc[4 * NPATCH];
__device__ unsigned int g_count;      // zero-init, reset by last block

// One thread = one 4-col x 20-row strip of a patch (20 float4 loads, stride 240 floats).
// Warp at fixed row-step reads 512 contiguous bytes. Last finished block finalizes.
__global__ void __launch_bounds__(256) patch_sums_kernel(
    const float* __restrict__ pred, const float* __restrict__ gt,
    int pred_blocks, int nstrips_pred, int total_blocks, int B,
    float* __restrict__ out) {
    __shared__ float s_s[NPATCH];
    __shared__ float s_ss[NPATCH];
    for (int i = threadIdx.x; i < NPATCH; i += blockDim.x) {
        s_s[i] = 0.0f;
        s_ss[i] = 0.0f;
    }
    __syncthreads();

    const float* src;
    int accOff, id, nmax;
    if (blockIdx.x < pred_blocks) {
        src = pred; accOff = 0;
        id = blockIdx.x * blockDim.x + threadIdx.x;
        nmax = nstrips_pred;
    } else {
        src = gt; accOff = 2 * NPATCH;
        id = (blockIdx.x - pred_blocks) * blockDim.x + threadIdx.x;
        nmax = STRIPS_PER_IMG;
    }

    if (id < nmax) {
        int img  = id / STRIPS_PER_IMG;
        int rem  = id % STRIPS_PER_IMG;
        int band = rem / 60;            // patch row g1
        int s    = rem % 60;            // float4 column index
        int patch = band * GSZ + s / 5; // g1*12 + g2

        const float4* p4 = reinterpret_cast<const float4*>(
            src + (size_t)img * IMG_ELEMS + (size_t)band * (PSZ * HW) + (size_t)s * 4);

        float s0 = 0.f, s1 = 0.f, s2 = 0.f, s3 = 0.f;
        float q0 = 0.f, q1 = 0.f, q2 = 0.f, q3 = 0.f;
#pragma unroll
        for (int r = 0; r < PSZ; r += 4) {
            float4 a = __ldcs(&p4[(size_t)r * 60]);
            float4 b = __ldcs(&p4[(size_t)(r + 1) * 60]);
            float4 c = __ldcs(&p4[(size_t)(r + 2) * 60]);
            float4 d = __ldcs(&p4[(size_t)(r + 3) * 60]);
            s0 += (a.x + a.y) + (a.z + a.w);
            q0 += (a.x * a.x + a.y * a.y) + (a.z * a.z + a.w * a.w);
            s1 += (b.x + b.y) + (b.z + b.w);
            q1 += (b.x * b.x + b.y * b.y) + (b.z * b.z + b.w * b.w);
            s2 += (c.x + c.y) + (c.z + c.w);
            q2 += (c.x * c.x + c.y * c.y) + (c.z * c.z + c.w * c.w);
            s3 += (d.x + d.y) + (d.z + d.w);
            q3 += (d.x * d.x + d.y * d.y) + (d.z * d.z + d.w * d.w);
        }
        atomicAdd(&s_s[patch],  (s0 + s1) + (s2 + s3));
        atomicAdd(&s_ss[patch], (q0 + q1) + (q2 + q3));
    }
    __syncthreads();

    for (int i = threadIdx.x; i < NPATCH; i += blockDim.x) {
        float a = s_s[i], b = s_ss[i];
        if (a != 0.0f || b != 0.0f) {
            atomicAdd(&g_acc[accOff + i],          (double)a);
            atomicAdd(&g_acc[accOff + NPATCH + i], (double)b);
        }
    }

    // ---- last-block-done finalization ----
    __shared__ bool s_last;
    __threadfence();
    if (threadIdx.x == 0) {
        unsigned int prev = atomicAdd(&g_count, 1u);
        s_last = (prev == (unsigned int)(total_blocks - 1));
    }
    __syncthreads();
    if (!s_last) return;

    __shared__ double red[256];
    __shared__ double sh_m;
    int t = threadIdx.x;
    volatile double* acc = g_acc;

    // global mean m from total pred sum
    red[t] = (t < NPATCH) ? acc[t] : 0.0;
    __syncthreads();
    for (int off = 128; off > 0; off >>= 1) {
        if (t < off) red[t] += red[t + off];
        __syncthreads();
    }
    if (t == 0) sh_m = red[0] / ((double)B * IMG_ELEMS);
    __syncthreads();
    double m = sh_m;

    double contrib = 0.0;
    if (t < NPATCH) {
        double n_pred = (double)B * PSZ * PSZ;
        double pv = acc[NPATCH + t] / n_pred
                  - 2.0 * m * (acc[t] / n_pred) + m * m;
        double n_gt = (double)(PSZ * PSZ);
        double gv = acc[3 * NPATCH + t] / n_gt
                  - 2.0 * m * (acc[2 * NPATCH + t] / n_gt) + m * m;
        double d = pv - gv;
        contrib = d * d;
    }
    __syncthreads();
    red[t] = contrib;
    __syncthreads();
    for (int off = 128; off > 0; off >>= 1) {
        if (t < off) red[t] += red[t + off];
        __syncthreads();
    }
    if (t == 0) out[0] = (float)(red[0] * 0.5 / 12.0);

    // re-zero scratch for the next graph replay
    __syncthreads();
    for (int i = t; i < 4 * NPATCH; i += blockDim.x) g_acc[i] = 0.0;
    if (t == 0) g_count = 0u;
}

extern "C" void kernel_launch(void* const* d_in, const int* in_sizes, int n_in,
                              void* d_out, int out_size) {
    const float* pred = (const float*)d_in[0];
    const float* gt   = (const float*)d_in[1];
    float* out        = (float*)d_out;

    int B = in_sizes[0] / IMG_ELEMS;
    int nstrips_pred = B * STRIPS_PER_IMG;                       // 368640 @ B=512

    int threads = 256;
    int pred_blocks = (nstrips_pred + threads - 1) / threads;    // 1440
    int gt_blocks   = (STRIPS_PER_IMG + threads - 1) / threads;  // 3
    int total_blocks = pred_blocks + gt_blocks;

    patch_sums_kernel<<<total_blocks, threads>>>(pred, gt, pred_blocks,
                                                 nstrips_pred, total_blocks, B, out);
}

// round 4
// speedup vs baseline: 1.2913x; 1.0010x over previous
#include <cuda_runtime.h>
#include <cuda_bf16.h>

#define HW   240
#define PSZ  20
#define GSZ  12
#define NPATCH (GSZ * GSZ)            // 144
#define HSTRIPS_PER_IMG 1440          // 12 bands * 2 halves * 60 float4-cols
#define IMG_ELEMS (HW * HW)           // 57600

// [0..143] pred sum, [144..287] pred sumsq, [288..431] gt sum, [432..575] gt sumsq
// Zero at module load; last block re-zeros after use -> graph-replay safe.
__device__ double g_acc[4 * NPATCH];
__device__ unsigned int g_count;      // zero-init, reset by last block

// One thread = 4 cols x 10 rows (half of a patch strip). All 10 float4 loads
// are front-batched (independent) for MLP ~10. Warp at fixed row reads 512
// contiguous bytes. Last finished block computes the loss.
__global__ void __launch_bounds__(256) patch_sums_kernel(
    const float* __restrict__ pred, const float* __restrict__ gt,
    int pred_blocks, int nhalf_pred, int total_blocks, int B,
    float* __restrict__ out) {
    __shared__ float s_s[NPATCH];
    __shared__ float s_ss[NPATCH];
    for (int i = threadIdx.x; i < NPATCH; i += blockDim.x) {
        s_s[i] = 0.0f;
        s_ss[i] = 0.0f;
    }
    __syncthreads();

    const float* src;
    int accOff, id, nmax;
    if (blockIdx.x < pred_blocks) {
        src = pred; accOff = 0;
        id = blockIdx.x * blockDim.x + threadIdx.x;
        nmax = nhalf_pred;
    } else {
        src = gt; accOff = 2 * NPATCH;
        id = (blockIdx.x - pred_blocks) * blockDim.x + threadIdx.x;
        nmax = HSTRIPS_PER_IMG;
    }

    if (id < nmax) {
        int img   = id / HSTRIPS_PER_IMG;
        int rem   = id % HSTRIPS_PER_IMG;
        int band  = rem / 120;            // patch row g1 (0..11)
        int rem2  = rem % 120;
        int half  = rem2 / 60;            // rows 0-9 or 10-19
        int s     = rem2 % 60;            // float4 column index
        int patch = band * GSZ + s / 5;   // g1*12 + g2

        const float4* p4 = reinterpret_cast<const float4*>(
            src + (size_t)img * IMG_ELEMS + (size_t)band * (PSZ * HW)
                + (size_t)half * (10 * HW) + (size_t)s * 4);

        float4 v[10];
#pragma unroll
        for (int r = 0; r < 10; r++) v[r] = __ldcs(&p4[(size_t)r * 60]);

        float s0 = 0.f, s1 = 0.f, q0 = 0.f, q1 = 0.f;
#pragma unroll
        for (int r = 0; r < 10; r += 2) {
            float4 a = v[r], b = v[r + 1];
            s0 += (a.x + a.y) + (a.z + a.w);
            q0 += (a.x * a.x + a.y * a.y) + (a.z * a.z + a.w * a.w);
            s1 += (b.x + b.y) + (b.z + b.w);
            q1 += (b.x * b.x + b.y * b.y) + (b.z * b.z + b.w * b.w);
        }
        atomicAdd(&s_s[patch],  s0 + s1);
        atomicAdd(&s_ss[patch], q0 + q1);
    }
    __syncthreads();

    for (int i = threadIdx.x; i < NPATCH; i += blockDim.x) {
        float a = s_s[i], b = s_ss[i];
        if (a != 0.0f || b != 0.0f) {
            atomicAdd(&g_acc[accOff + i],          (double)a);
            atomicAdd(&g_acc[accOff + NPATCH + i], (double)b);
        }
    }

    // ---- last-block-done finalization ----
    __shared__ bool s_last;
    __threadfence();
    if (threadIdx.x == 0) {
        unsigned int prev = atomicAdd(&g_count, 1u);
        s_last = (prev == (unsigned int)(total_blocks - 1));
    }
    __syncthreads();
    if (!s_last) return;

    __shared__ double red[256];
    __shared__ double sh_m;
    int t = threadIdx.x;
    volatile double* acc = g_acc;

    // global mean m from total pred sum
    red[t] = (t < NPATCH) ? acc[t] : 0.0;
    __syncthreads();
    for (int off = 128; off > 0; off >>= 1) {
        if (t < off) red[t] += red[t + off];
        __syncthreads();
    }
    if (t == 0) sh_m = red[0] / ((double)B * IMG_ELEMS);
    __syncthreads();
    double m = sh_m;

    double contrib = 0.0;
    if (t < NPATCH) {
        double n_pred = (double)B * PSZ * PSZ;
        double pv = acc[NPATCH + t] / n_pred
                  - 2.0 * m * (acc[t] / n_pred) + m * m;
        double n_gt = (double)(PSZ * PSZ);
        double gv = acc[3 * NPATCH + t] / n_gt
                  - 2.0 * m * (acc[2 * NPATCH + t] / n_gt) + m * m;
        double d = pv - gv;
        contrib = d * d;
    }
    __syncthreads();
    red[t] = contrib;
    __syncthreads();
    for (int off = 128; off > 0; off >>= 1) {
        if (t < off) red[t] += red[t + off];
        __syncthreads();
    }
    if (t == 0) out[0] = (float)(red[0] * 0.5 / 12.0);

    // re-zero scratch for the next graph replay
    __syncthreads();
    for (int i = t; i < 4 * NPATCH; i += blockDim.x) g_acc[i] = 0.0;
    if (t == 0) g_count = 0u;
}

extern "C" void kernel_launch(void* const* d_in, const int* in_sizes, int n_in,
                              void* d_out, int out_size) {
    const float* pred = (const float*)d_in[0];
    const float* gt   = (const float*)d_in[1];
    float* out        = (float*)d_out;

    int B = in_sizes[0] / IMG_ELEMS;
    int nhalf_pred = B * HSTRIPS_PER_IMG;                        // 737280 @ B=512

    int threads = 256;
    int pred_blocks = (nhalf_pred + threads - 1) / threads;      // 2880
    int gt_blocks   = (HSTRIPS_PER_IMG + threads - 1) / threads; // 6
    int total_blocks = pred_blocks + gt_blocks;

    patch_sums_kernel<<<total_blocks, threads>>>(pred, gt, pred_blocks,
                                                 nhalf_pred, total_blocks, B, out);
}

// round 6
// speedup vs baseline: 1.4054x; 1.0884x over previous
#include <cuda_runtime.h>
#include <cuda_bf16.h>
#include <cstdint>

#define HW   240
#define PSZ  20
#define GSZ  12
#define NPATCH (GSZ * GSZ)            // 144
#define IMG_ELEMS (HW * HW)           // 57600
#define CHUNK_FLOATS 2400             // half band: 10 rows x 240 cols
#define CHUNK_BYTES  9600
#define NSTAGES 4
#define NB 23                         // pred blocks per band

// [0..143] pred sum, [144..287] pred sumsq, [288..431] gt sum, [432..575] gt sumsq
__device__ double g_acc[4 * NPATCH];
__device__ unsigned int g_count;

__device__ __forceinline__ uint32_t smem_u32(const void* p) {
    uint32_t a;
    asm("{ .reg .u64 t; cvta.to.shared.u64 t, %1; cvt.u32.u64 %0, t; }" : "=r"(a) : "l"(p));
    return a;
}
__device__ __forceinline__ void mbar_init(uint32_t mbar, uint32_t cnt) {
    asm volatile("mbarrier.init.shared.b64 [%0], %1;" :: "r"(mbar), "r"(cnt) : "memory");
}
__device__ __forceinline__ void mbar_expect_tx(uint32_t mbar, uint32_t bytes) {
    asm volatile("mbarrier.arrive.expect_tx.shared.b64 _, [%0], %1;" :: "r"(mbar), "r"(bytes) : "memory");
}
__device__ __forceinline__ void mbar_wait(uint32_t mbar, uint32_t parity) {
    asm volatile(
        "{\n\t.reg .pred P;\n"
        "W_%=:\n\t"
        "mbarrier.try_wait.parity.acquire.cta.shared::cta.b64 P, [%0], %1, 0x989680;\n\t"
        "@P bra D_%=;\n\t"
        "bra W_%=;\n"
        "D_%=:\n\t}"
        :: "r"(mbar), "r"(parity) : "memory");
}
__device__ __forceinline__ void tma_1d(uint32_t dst, const void* src, uint32_t bytes, uint32_t mbar) {
    asm volatile(
        "cp.async.bulk.shared::cta.global.mbarrier::complete_tx::bytes [%0], [%1], %2, [%3];"
        :: "r"(dst), "l"(src), "r"(bytes), "r"(mbar) : "memory");
}
__device__ __forceinline__ void fence_async() {
    asm volatile("fence.proxy.async.shared::cta;" ::: "memory");
}

// grid = 12*NB pred blocks + 12 gt blocks. Block owns a fixed band (patch row):
// every thread's patch is fixed -> register accumulation across all chunks.
__global__ void __launch_bounds__(256) patch_sums_kernel(
    const float* __restrict__ pred, const float* __restrict__ gt,
    int B, int total_blocks, float* __restrict__ out) {
    __shared__ __align__(16) float buf[NSTAGES][CHUNK_FLOATS];
    __shared__ __align__(8) unsigned long long bar[NSTAGES];
    __shared__ float bs[GSZ], bq[GSZ];

    const int tid = threadIdx.x;
    const int bid = blockIdx.x;

    const float* base;
    int band, blkInBand, nimg, accOff;
    if (bid < 12 * NB) {
        band = bid / NB; blkInBand = bid % NB;
        base = pred; accOff = 0;
        nimg = (B - blkInBand + NB - 1) / NB;      // images: blkInBand, +NB, ...
        if (B <= blkInBand) nimg = 0;
    } else {
        band = bid - 12 * NB; blkInBand = 0;
        base = gt; accOff = 2 * NPATCH;
        nimg = 1;
    }
    const int nchunks = 2 * nimg;

    if (tid < GSZ) { bs[tid] = 0.0f; bq[tid] = 0.0f; }
    if (tid == 0) {
        for (int k = 0; k < NSTAGES; k++) mbar_init(smem_u32(&bar[k]), 1);
        fence_async();
    }
    __syncthreads();

    // chunk c -> image i = blkInBand + (c>>1)*NB, half h = c&1
    auto chunk_src = [&](int c) -> const float* {
        int i = blkInBand + (c >> 1) * NB;
        int h = c & 1;
        return base + (size_t)i * IMG_ELEMS + (size_t)band * (PSZ * HW) + (size_t)h * CHUNK_FLOATS;
    };

    if (tid == 0) {
        int pro = nchunks < NSTAGES ? nchunks : NSTAGES;
        for (int k = 0; k < pro; k++) {
            uint32_t mb = smem_u32(&bar[k]);
            mbar_expect_tx(mb, CHUNK_BYTES);
            tma_1d(smem_u32(&buf[k][0]), chunk_src(k), CHUNK_BYTES, mb);
        }
    }

    const int col4   = tid % 60;       // float4 column in row
    const int rowgrp = tid / 60;       // 0..3 (tid<240 active)
    const int pc     = col4 / 5;       // patch column 0..11
    float s_acc = 0.0f, q_acc = 0.0f;

    for (int c = 0; c < nchunks; c++) {
        const int st = c & (NSTAGES - 1);
        mbar_wait(smem_u32(&bar[st]), (c >> 2) & 1);

        if (tid < 240) {
            const float* bp = &buf[st][0];
#pragma unroll
            for (int k = 0; k < 3; k++) {
                int row = rowgrp + 4 * k;          // rows rowgrp, +4, +8 (<10)
                if (row < 10) {
                    float4 v = *reinterpret_cast<const float4*>(bp + row * HW + col4 * 4);
                    s_acc += (v.x + v.y) + (v.z + v.w);
                    q_acc += (v.x * v.x + v.y * v.y) + (v.z * v.z + v.w * v.w);
                }
            }
        }
        __syncthreads();                           // all reads of stage st done

        if (tid == 0 && c + NSTAGES < nchunks) {
            fence_async();
            uint32_t mb = smem_u32(&bar[st]);
            mbar_expect_tx(mb, CHUNK_BYTES);
            tma_1d(smem_u32(&buf[st][0]), chunk_src(c + NSTAGES), CHUNK_BYTES, mb);
        }
    }

    // block reduce: 20 threads per patch column -> shared -> global
    if (tid < 240) {
        atomicAdd(&bs[pc], s_acc);
        atomicAdd(&bq[pc], q_acc);
    }
    __syncthreads();
    if (tid < GSZ && nchunks > 0) {
        atomicAdd(&g_acc[accOff + band * GSZ + tid],          (double)bs[tid]);
        atomicAdd(&g_acc[accOff + NPATCH + band * GSZ + tid], (double)bq[tid]);
    }

    // ---- last-block-done finalization ----
    __shared__ bool s_last;
    __threadfence();
    if (tid == 0) {
        unsigned int prev = atomicAdd(&g_count, 1u);
        s_last = (prev == (unsigned int)(total_blocks - 1));
    }
    __syncthreads();
    if (!s_last) return;

    __shared__ double red[256];
    __shared__ double sh_m;
    volatile double* acc = g_acc;
    int t = tid;

    red[t] = (t < NPATCH) ? acc[t] : 0.0;
    __syncthreads();
    for (int off = 128; off > 0; off >>= 1) {
        if (t < off) red[t] += red[t + off];
        __syncthreads();
    }
    if (t == 0) sh_m = red[0] / ((double)B * IMG_ELEMS);
    __syncthreads();
    double m = sh_m;

    double contrib = 0.0;
    if (t < NPATCH) {
        double n_pred = (double)B * PSZ * PSZ;
        double pv = acc[NPATCH + t] / n_pred - 2.0 * m * (acc[t] / n_pred) + m * m;
        double n_gt = (double)(PSZ * PSZ);
        double gv = acc[3 * NPATCH + t] / n_gt - 2.0 * m * (acc[2 * NPATCH + t] / n_gt) + m * m;
        double d = pv - gv;
        contrib = d * d;
    }
    __syncthreads();
    red[t] = contrib;
    __syncthreads();
    for (int off = 128; off > 0; off >>= 1) {
        if (t < off) red[t] += red[t + off];
        __syncthreads();
    }
    if (t == 0) out[0] = (float)(red[0] * 0.5 / 12.0);

    __syncthreads();
    for (int i = t; i < 4 * NPATCH; i += blockDim.x) g_acc[i] = 0.0;
    if (t == 0) g_count = 0u;
}

extern "C" void kernel_launch(void* const* d_in, const int* in_sizes, int n_in,
                              void* d_out, int out_size) {
    const float* pred = (const float*)d_in[0];
    const float* gt   = (const float*)d_in[1];
    float* out        = (float*)d_out;

    int B = in_sizes[0] / IMG_ELEMS;
    int total_blocks = 12 * NB + 12;   // 288: one wave on 148 SMs @ 2 blocks/SM

    patch_sums_kernel<<<total_blocks, 256>>>(pred, gt, B, total_blocks, out);
}